// round 7
// baseline (speedup 1.0000x reference)
#include <cuda_runtime.h>
#include <cstdint>

#define Bn 128
#define Tn 512
#define Dn 128
#define NCOL (Bn * Tn)                  // 65536 columns / rows
#define NCHUNK 4                        // row chunks per column scan
#define CHUNK 128

// Copy: warp per row, 8 rows per 256-thread block. Split 60/40.
#define SPLIT_ROW 39424                 // multiple of 8
#define CPA_BLOCKS (SPLIT_ROW / 8)              // 4928
#define CPB_BLOCKS ((NCOL - SPLIT_ROW) / 8)     // 3264

// K1 roles
#define SCAN_BLOCKS 1024                // 128 b x 2 colblocks x 4 chunks
#define RAMP_BLOCKS 128
#define K1_BLOCKS (SCAN_BLOCKS + RAMP_BLOCKS + CPA_BLOCKS)

// K2 roles
#define SPMM_BLOCKS (NCOL / 8)          // 8192: warp per column
#define K2_BLOCKS (SPMM_BLOCKS + CPB_BLOCKS)

// Per-(column, chunk) support range, interleaved for 8B vector merge loads.
__device__ short g_s[NCOL * NCHUNK];
__device__ short g_e[NCOL * NCHUNK];

// int32 vs int64 auto-detect: values >= 1, so word[1]==0 <=> int64 buffer.
__device__ __forceinline__ int load_len(const int* __restrict__ raw, int b) {
    int stride = (raw[1] == 0) ? 2 : 1;
    return __ldg(raw + b * stride);
}

// Warp-per-row sparse-aware copy. len/alen hoisted once per 2KB row; reads
// only cols < alen (sources beyond are genuinely zero); writes the full row
// (clears 0xAA poison). Rows >= len are zero-filled with no reads.
__device__ __forceinline__ void copy_rows(
    const float* __restrict__ stb, float* __restrict__ out,
    const int* __restrict__ len_raw, const int* __restrict__ alen_raw,
    int row_base, int tid)
{
    int warp = tid >> 5;
    int lane = tid & 31;
    int row = row_base + warp;                  // row in [0, Bn*Tn)
    int b = row >> 9;
    int r = row & (Tn - 1);
    int len  = load_len(len_raw, b);
    int alen = load_len(alen_raw, b);
    int alen4 = (alen + 3) >> 2;                // float4 bound

    const float4* src = (const float4*)(stb + (size_t)row * Tn);
    float4* dst = (float4*)(out + (size_t)row * Tn);
    const float4 z = make_float4(0.f, 0.f, 0.f, 0.f);

    if (r >= len) {
#pragma unroll
        for (int k = 0; k < 4; ++k) dst[lane + k * 32] = z;
    } else {
        float4 v[4];
#pragma unroll
        for (int k = 0; k < 4; ++k) {
            int idx = lane + k * 32;
            v[k] = (idx < alen4) ? __ldg(src + idx) : z;   // 4 independent loads
        }
#pragma unroll
        for (int k = 0; k < 4; ++k) dst[lane + k * 32] = v[k];
    }
}

// ---------------------------------------------------------------------------
// K1: chunked column-support scan + ramps + copy rows [0, SPLIT_ROW).
// ---------------------------------------------------------------------------
__global__ void __launch_bounds__(256) k1(
    const float* __restrict__ seqtoblur, float* __restrict__ out_stb,
    const float* __restrict__ bm,
    const int* __restrict__ len_raw, const int* __restrict__ alen_raw,
    float* __restrict__ R, float* __restrict__ aR,
    float* __restrict__ alen_out, int alen_mode)
{
    int blk = blockIdx.x;
    int tid = threadIdx.x;

    if (blk < SCAN_BLOCKS) {
        // blk = (b * 2 + colblk) * NCHUNK + c
        int c = blk & (NCHUNK - 1);
        int bc = blk >> 2;
        int b = bc >> 1;
        int i = ((bc & 1) << 8) + tid;          // column; lanes adjacent
        int col = b * Tn + i;
        int len  = load_len(len_raw, b);
        int alen = load_len(alen_raw, b);
        int t0 = c * CHUNK;
        int n = min(CHUNK, len - t0);           // rows in this chunk, may be <=0
        int s = Tn, e = -1;
        // len<=2 => eye case handled in spmm; cols >= alen are all zero.
        if (len > 2 && (i & ~31) < alen && n > 0) {
            const float* colp = bm + (size_t)b * Tn * Tn + (size_t)t0 * Tn + i;
#pragma unroll 8
            for (int t = 0; t < n; ++t) {
                float v = __ldg(colp + (size_t)t * Tn);
                if (v != 0.0f) { s = (t < s) ? t : s; e = t; }
            }
        }
        g_s[col * NCHUNK + c] = (short)(e >= 0 ? s + t0 : Tn);
        g_e[col * NCHUNK + c] = (short)(e >= 0 ? e + t0 : -1);
        return;
    }

    if (blk < SCAN_BLOCKS + RAMP_BLOCKS) {
        int b = blk - SCAN_BLOCKS;
        int l  = load_len(len_raw, b);
        int al = load_len(alen_raw, b);
        float invl  = 1.0f / fmaxf((float)l,  1.0f);
        float inval = 1.0f / fmaxf((float)al, 1.0f);
#pragma unroll
        for (int t = tid; t < Tn; t += 256) {
            R[b * Tn + t]  = (t < l)  ? (float)(t + 1) * invl  : 0.0f;
            aR[b * Tn + t] = (t < al) ? (float)(t + 1) * inval : 0.0f;
        }
        if (tid == 0) {
            if (alen_mode == 1)      alen_out[b] = (float)al;
            else if (alen_mode == 2) ((long long*)alen_out)[b] = (long long)al;
        }
        return;
    }

    // Copy slice A: rows [0, SPLIT_ROW).
    {
        int cblk = blk - (SCAN_BLOCKS + RAMP_BLOCKS);
        copy_rows(seqtoblur, out_stb, len_raw, alen_raw, cblk * 8, tid);
    }
}

// ---------------------------------------------------------------------------
// K2: sparse gather (warp per column) + copy rows [SPLIT_ROW, NCOL).
// ---------------------------------------------------------------------------
__global__ void __launch_bounds__(256) k2(
    const float* __restrict__ seq,
    const float* __restrict__ seqtoblur, float* __restrict__ out_stb,
    const float* __restrict__ bm,
    const int* __restrict__ len_raw, const int* __restrict__ alen_raw,
    float* __restrict__ out_avged)
{
    int blk = blockIdx.x;
    int tid = threadIdx.x;

    if (blk < SPMM_BLOCKS) {
        int warp = tid >> 5;
        int lane = tid & 31;
        int col = blk * 8 + warp;
        int b = col >> 9;
        int i = col & (Tn - 1);
        int len = load_len(len_raw, b);

        const float4* seqb = (const float4*)(seq + (size_t)b * Tn * Dn) + lane;
        float4* dst = (float4*)(out_avged + ((size_t)b * Tn + i) * Dn);

        if (len <= 2) {
            // BlurMat = eye(512): avged_seq row i = seq row i.
            dst[lane] = __ldg(seqb + (size_t)i * (Dn / 4));
            return;
        }
        // Merge the NCHUNK ranges via two 8-byte vector loads.
        const short4 sv = *(const short4*)(g_s + col * NCHUNK);
        const short4 ev = *(const short4*)(g_e + col * NCHUNK);
        int s = min(min((int)sv.x, (int)sv.y), min((int)sv.z, (int)sv.w));
        int e = max(max((int)ev.x, (int)ev.y), max((int)ev.z, (int)ev.w));

        const float* colp = bm + (size_t)b * Tn * Tn + i;
        float4 acc = make_float4(0.f, 0.f, 0.f, 0.f);
        for (int t = s; t <= e; ++t) {
            float w = __ldg(colp + (size_t)t * Tn);        // warp-broadcast
            float4 v = __ldg(seqb + (size_t)t * (Dn / 4));
            acc.x = fmaf(w, v.x, acc.x);
            acc.y = fmaf(w, v.y, acc.y);
            acc.z = fmaf(w, v.z, acc.z);
            acc.w = fmaf(w, v.w, acc.w);
        }
        // Full write clears 0xAA poison + handles k==5 all-zero branch.
        dst[lane] = acc;
        return;
    }

    // Copy slice B: rows [SPLIT_ROW, NCOL).
    {
        int cblk = blk - SPMM_BLOCKS;
        copy_rows(seqtoblur, out_stb, len_raw, alen_raw,
                  SPLIT_ROW + cblk * 8, tid);
    }
}

extern "C" void kernel_launch(void* const* d_in, const int* in_sizes, int n_in,
                              void* d_out, int out_size) {
    const float* seq       = (const float*)d_in[0];
    const int*   len_raw   = (const int*)d_in[1];
    const float* seqtoblur = (const float*)d_in[2];
    const float* blurmat   = (const float*)d_in[3];
    const int*   alen_raw  = (const int*)d_in[4];

    float* out = (float*)d_out;

    const size_t OFF_AVG  = (size_t)Bn * Tn * Tn;             // 33,554,432
    const size_t OFF_R    = OFF_AVG + (size_t)Bn * Tn * Dn;   // 41,943,040
    const size_t OFF_AR   = OFF_R + (size_t)Bn * Tn;          // 42,008,576
    const size_t OFF_ALEN = OFF_AR + (size_t)Bn * Tn;         // 42,074,112

    long long rem = (long long)out_size - (long long)OFF_ALEN;
    int alen_mode = 0;
    if (rem == Bn) alen_mode = 1;          // avged_len as float32
    else if (rem == 2 * Bn) alen_mode = 2; // avged_len as raw int64

    k1<<<K1_BLOCKS, 256>>>(seqtoblur, out, blurmat,
                           len_raw, alen_raw,
                           out + OFF_R, out + OFF_AR,
                           out + OFF_ALEN, alen_mode);

    k2<<<K2_BLOCKS, 256>>>(seq, seqtoblur, out, blurmat,
                           len_raw, alen_raw, out + OFF_AVG);
}

// round 8
// speedup vs baseline: 1.0329x; 1.0329x over previous
#include <cuda_runtime.h>
#include <cstdint>

#define Bn 128
#define Tn 512
#define Dn 128
#define NCOL (Bn * Tn)                  // 65536 columns
#define COPY_N4 (Bn * Tn * Tn / 4)      // 8,388,608 float4
#define NCHUNK 4                        // row chunks per column scan
#define CHUNK 128

// K1 roles
#define SCAN_BLOCKS 1024                // 128 b x 2 colblocks x 4 chunks
#define RAMP_BLOCKS 128
#define CPA_BLOCKS 2048
#define K1_BLOCKS (SCAN_BLOCKS + RAMP_BLOCKS + CPA_BLOCKS)
#define CPA_N4 5242880                  // 62.5% of the copy

// K2 roles
#define SPMM_BLOCKS (NCOL / 8)          // 8192: warp per column
#define CPB_BLOCKS 2048
#define K2_BLOCKS (SPMM_BLOCKS + CPB_BLOCKS)

// Per-(column, chunk) support range, interleaved for 8B vector merge loads.
__device__ short g_s[NCOL * NCHUNK];
__device__ short g_e[NCOL * NCHUNK];

// int32 vs int64 auto-detect: values >= 1, so word[1]==0 <=> int64 buffer.
__device__ __forceinline__ int load_len(const int* __restrict__ raw, int b) {
    int stride = (raw[1] == 0) ? 2 : 1;
    return __ldg(raw + b * stride);
}

// Sparse-aware grid-stride copy with SMEM len tables. Each iteration's 4
// float4s lie in ONE row (i % 4 == 0), so one len/alen4 pair per 64B.
// Reads only inside the len x alen corner; writes everything (0xAA poison).
__device__ __forceinline__ void copy_sparse(
    const float4* __restrict__ s4, float4* __restrict__ d4,
    const int* __restrict__ sh_len, const int* __restrict__ sh_alen4,
    int base, int end, int tid_global, int nthreads)
{
    const float4 z = make_float4(0.f, 0.f, 0.f, 0.f);
    int i = base + tid_global * 4;
    int stride = nthreads * 4;
    for (; i + 3 < end; i += stride) {
        int b = i >> 16;
        int r = (i >> 7) & (Tn - 1);
        int c4 = i & 127;
        int len   = sh_len[b];
        int alen4 = sh_alen4[b];
        float4 v[4];
        if (r < len) {
#pragma unroll
            for (int k = 0; k < 4; ++k)
                v[k] = (c4 + k < alen4) ? __ldg(s4 + i + k) : z;
        } else {
#pragma unroll
            for (int k = 0; k < 4; ++k) v[k] = z;
        }
#pragma unroll
        for (int k = 0; k < 4; ++k) d4[i + k] = v[k];
    }
    for (; i < end; ++i) {   // safety tail (counts are multiples of 4)
        int b = i >> 16;
        int r = (i >> 7) & (Tn - 1);
        int c4 = i & 127;
        d4[i] = (r < sh_len[b] && c4 < sh_alen4[b]) ? __ldg(s4 + i) : z;
    }
}

// ---------------------------------------------------------------------------
// K1: chunked column-support scan + ramps + copy slice A.
// ---------------------------------------------------------------------------
__global__ void __launch_bounds__(256) k1(
    const float* __restrict__ seqtoblur, float* __restrict__ out_stb,
    const float* __restrict__ bm,
    const int* __restrict__ len_raw, const int* __restrict__ alen_raw,
    float* __restrict__ R, float* __restrict__ aR,
    float* __restrict__ alen_out, int alen_mode)
{
    int blk = blockIdx.x;
    int tid = threadIdx.x;

    if (blk < SCAN_BLOCKS) {
        // blk = (b * 2 + colblk) * NCHUNK + c
        int c = blk & (NCHUNK - 1);
        int bc = blk >> 2;
        int b = bc >> 1;
        int i = ((bc & 1) << 8) + tid;          // column; lanes adjacent
        int col = b * Tn + i;
        int len  = load_len(len_raw, b);
        int alen = load_len(alen_raw, b);
        int t0 = c * CHUNK;
        int n = min(CHUNK, len - t0);           // rows in this chunk, may be <=0
        int s = Tn, e = -1;
        // len<=2 => eye case handled in spmm; cols >= alen are all zero.
        if (len > 2 && (i & ~31) < alen && n > 0) {
            const float* colp = bm + (size_t)b * Tn * Tn + (size_t)t0 * Tn + i;
#pragma unroll 8
            for (int t = 0; t < n; ++t) {
                float v = __ldg(colp + (size_t)t * Tn);
                if (v != 0.0f) { s = (t < s) ? t : s; e = t; }
            }
        }
        g_s[col * NCHUNK + c] = (short)(e >= 0 ? s + t0 : Tn);
        g_e[col * NCHUNK + c] = (short)(e >= 0 ? e + t0 : -1);
        return;
    }

    if (blk < SCAN_BLOCKS + RAMP_BLOCKS) {
        int b = blk - SCAN_BLOCKS;
        int l  = load_len(len_raw, b);
        int al = load_len(alen_raw, b);
        float invl  = 1.0f / fmaxf((float)l,  1.0f);
        float inval = 1.0f / fmaxf((float)al, 1.0f);
#pragma unroll
        for (int t = tid; t < Tn; t += 256) {
            R[b * Tn + t]  = (t < l)  ? (float)(t + 1) * invl  : 0.0f;
            aR[b * Tn + t] = (t < al) ? (float)(t + 1) * inval : 0.0f;
        }
        if (tid == 0) {
            if (alen_mode == 1)      alen_out[b] = (float)al;
            else if (alen_mode == 2) ((long long*)alen_out)[b] = (long long)al;
        }
        return;
    }

    // Copy slice A.
    {
        __shared__ int sh_len[Bn];
        __shared__ int sh_alen4[Bn];
        if (tid < Bn) {
            sh_len[tid] = load_len(len_raw, tid);
            sh_alen4[tid] = (load_len(alen_raw, tid) + 3) >> 2;
        }
        __syncthreads();
        int cblk = blk - (SCAN_BLOCKS + RAMP_BLOCKS);
        copy_sparse((const float4*)seqtoblur, (float4*)out_stb,
                    sh_len, sh_alen4,
                    0, CPA_N4, cblk * 256 + tid, CPA_BLOCKS * 256);
    }
}

// ---------------------------------------------------------------------------
// K2: sparse gather (warp per column) + copy slice B.
// ---------------------------------------------------------------------------
__global__ void __launch_bounds__(256) k2(
    const float* __restrict__ seq,
    const float* __restrict__ seqtoblur, float* __restrict__ out_stb,
    const float* __restrict__ bm,
    const int* __restrict__ len_raw, const int* __restrict__ alen_raw,
    float* __restrict__ out_avged)
{
    int blk = blockIdx.x;
    int tid = threadIdx.x;

    if (blk < SPMM_BLOCKS) {
        int warp = tid >> 5;
        int lane = tid & 31;
        int col = blk * 8 + warp;
        int b = col >> 9;
        int i = col & (Tn - 1);
        int len = load_len(len_raw, b);

        const float4* seqb = (const float4*)(seq + (size_t)b * Tn * Dn) + lane;
        float4* dst = (float4*)(out_avged + ((size_t)b * Tn + i) * Dn);

        if (len <= 2) {
            // BlurMat = eye(512): avged_seq row i = seq row i.
            dst[lane] = __ldg(seqb + (size_t)i * (Dn / 4));
            return;
        }
        // Merge the NCHUNK ranges via two 8-byte vector loads.
        const short4 sv = *(const short4*)(g_s + col * NCHUNK);
        const short4 ev = *(const short4*)(g_e + col * NCHUNK);
        int s = min(min((int)sv.x, (int)sv.y), min((int)sv.z, (int)sv.w));
        int e = max(max((int)ev.x, (int)ev.y), max((int)ev.z, (int)ev.w));

        const float* colp = bm + (size_t)b * Tn * Tn + i;
        float4 acc = make_float4(0.f, 0.f, 0.f, 0.f);
        for (int t = s; t <= e; ++t) {
            float w = __ldg(colp + (size_t)t * Tn);        // warp-broadcast
            float4 v = __ldg(seqb + (size_t)t * (Dn / 4));
            acc.x = fmaf(w, v.x, acc.x);
            acc.y = fmaf(w, v.y, acc.y);
            acc.z = fmaf(w, v.z, acc.z);
            acc.w = fmaf(w, v.w, acc.w);
        }
        // Full write clears 0xAA poison + handles k==5 all-zero branch.
        dst[lane] = acc;
        return;
    }

    // Copy slice B.
    {
        __shared__ int sh_len[Bn];
        __shared__ int sh_alen4[Bn];
        if (tid < Bn) {
            sh_len[tid] = load_len(len_raw, tid);
            sh_alen4[tid] = (load_len(alen_raw, tid) + 3) >> 2;
        }
        __syncthreads();
        int cblk = blk - SPMM_BLOCKS;
        copy_sparse((const float4*)seqtoblur, (float4*)out_stb,
                    sh_len, sh_alen4,
                    CPA_N4, COPY_N4, cblk * 256 + tid, CPB_BLOCKS * 256);
    }
}

extern "C" void kernel_launch(void* const* d_in, const int* in_sizes, int n_in,
                              void* d_out, int out_size) {
    const float* seq       = (const float*)d_in[0];
    const int*   len_raw   = (const int*)d_in[1];
    const float* seqtoblur = (const float*)d_in[2];
    const float* blurmat   = (const float*)d_in[3];
    const int*   alen_raw  = (const int*)d_in[4];

    float* out = (float*)d_out;

    const size_t OFF_AVG  = (size_t)Bn * Tn * Tn;             // 33,554,432
    const size_t OFF_R    = OFF_AVG + (size_t)Bn * Tn * Dn;   // 41,943,040
    const size_t OFF_AR   = OFF_R + (size_t)Bn * Tn;          // 42,008,576
    const size_t OFF_ALEN = OFF_AR + (size_t)Bn * Tn;         // 42,074,112

    long long rem = (long long)out_size - (long long)OFF_ALEN;
    int alen_mode = 0;
    if (rem == Bn) alen_mode = 1;          // avged_len as float32
    else if (rem == 2 * Bn) alen_mode = 2; // avged_len as raw int64

    k1<<<K1_BLOCKS, 256>>>(seqtoblur, out, blurmat,
                           len_raw, alen_raw,
                           out + OFF_R, out + OFF_AR,
                           out + OFF_ALEN, alen_mode);

    k2<<<K2_BLOCKS, 256>>>(seq, seqtoblur, out, blurmat,
                           len_raw, alen_raw, out + OFF_AVG);
}